// round 4
// baseline (speedup 1.0000x reference)
#include <cuda_runtime.h>

// GraphSAGE on GB300: CSR-gather aggregation + register-tiled fp32 GEMM.
// Pipeline (all graph-capturable, scratch in __device__ globals):
//   Kd detect: edge_index dtype sniff (int32 vs int64 low/high words)
//   K0 fold:   W2lc = W2l@Wc, W2rc = W2r@Wc, bc2 = b2@Wc + bc        (tiny)
//   K1 zero:   cnt = 0
//   K2 hist:   cnt[dst]++ per edge
//   K3 scan:   off = exclusive_scan(cnt), cur = off                   (1 block)
//   K4 fill:   csr[cur[dst]++] = src
//   K5 agg1:   agg1[i] = mean_{e: dst=i} x[src[e]]   (16 thr/node, float4)
//   K6 layer1: h = relu(agg1@W1l + b1 + x@W1r); t = h@W2lc; r = h@W2rc
//              (64x64x64 tile GEMM, 4x4 microtiles, h stays in registers)
//   K7 final:  out[i] = mean_{e: dst=i} t[src[e]] + r[i] + bc2

#define NMAX 100000
#define EMAX 1600000

__device__ float  g_agg1[NMAX * 64];
__device__ float2 g_t[NMAX];
__device__ float2 g_r[NMAX];
__device__ int    g_cnt[NMAX];
__device__ int    g_off[NMAX + 1];
__device__ int    g_cur[NMAX];
__device__ int    g_csr[EMAX];
__device__ float  g_W2lc[128];
__device__ float  g_W2rc[128];
__device__ float  g_bc2[2];
__device__ int    g_is64;

// ---------------------------------------------------------------- Kd: dtype detect
// int64 little-endian with values < 2^31 => every odd 32-bit word is 0.
// int32 random indices => odd words ~U[0,1e5): P(8+ zeros) is negligible.
__global__ void sage_detect_kernel(const int* __restrict__ w) {
    if (threadIdx.x == 0) {
        int odd_nonzero = 0;
#pragma unroll
        for (int i = 1; i < 64; i += 2)
            if (w[i] != 0) odd_nonzero = 1;
        g_is64 = odd_nonzero ? 0 : 1;
    }
}

__device__ __forceinline__ int edge_val(const int* __restrict__ w, int is64, int idx) {
    // little-endian low word of int64, or plain int32
    return is64 ? w[2 * idx] : w[idx];
}

// ---------------------------------------------------------------- K0: fold
__global__ void sage_fold_kernel(const float* __restrict__ W2l,
                                 const float* __restrict__ b2,
                                 const float* __restrict__ W2r,
                                 const float* __restrict__ Wc,
                                 const float* __restrict__ bc) {
    int t = threadIdx.x;           // 128 threads: (k, c) pairs
    if (t < 128) {
        int k = t >> 1, c = t & 1;
        float s = 0.f, sr = 0.f;
#pragma unroll
        for (int m = 0; m < 64; m++) {
            float w = Wc[m * 2 + c];
            s  += W2l[k * 64 + m] * w;
            sr += W2r[k * 64 + m] * w;
        }
        g_W2lc[k * 2 + c] = s;
        g_W2rc[k * 2 + c] = sr;
    }
    if (t < 2) {
        float sb = 0.f;
        for (int m = 0; m < 64; m++) sb += b2[m] * Wc[m * 2 + t];
        g_bc2[t] = sb + bc[t];
    }
}

// ---------------------------------------------------------------- K1: zero
__global__ void sage_zero_cnt(int n) {
    int i = blockIdx.x * blockDim.x + threadIdx.x;
    if (i < n) g_cnt[i] = 0;
}

// ---------------------------------------------------------------- K2: hist
__global__ void sage_hist_kernel(const int* __restrict__ ei, int E, int nn) {
    int e = blockIdx.x * blockDim.x + threadIdx.x;
    if (e < E) {
        int dst = edge_val(ei, g_is64, E + e);
        if ((unsigned)dst < (unsigned)nn)
            atomicAdd(&g_cnt[dst], 1);
    }
}

// ---------------------------------------------------------------- K3: scan (single block, warp-shuffle)
__global__ void sage_scan_kernel(int n) {
    __shared__ int wsum[32];
    __shared__ int run_s;
    int t = threadIdx.x;
    int lane = t & 31, wid = t >> 5;
    if (t == 0) run_s = 0;
    __syncthreads();
    for (int base = 0; base < n; base += 1024) {
        int i = base + t;
        int v = (i < n) ? g_cnt[i] : 0;
        int x = v;
#pragma unroll
        for (int d = 1; d < 32; d <<= 1) {
            int y = __shfl_up_sync(0xffffffffu, x, d);
            if (lane >= d) x += y;
        }
        if (lane == 31) wsum[wid] = x;
        __syncthreads();
        if (wid == 0) {
            int w = wsum[lane];
            int xw = w;
#pragma unroll
            for (int d = 1; d < 32; d <<= 1) {
                int y = __shfl_up_sync(0xffffffffu, xw, d);
                if (lane >= d) xw += y;
            }
            wsum[lane] = xw;   // inclusive scan of warp sums
        }
        __syncthreads();
        int wexcl = (wid == 0) ? 0 : wsum[wid - 1];
        int excl = (x - v) + wexcl;
        int r = run_s;
        if (i < n) { g_off[i] = r + excl; g_cur[i] = r + excl; }
        int tot = wsum[31];
        __syncthreads();
        if (t == 0) run_s += tot;
        __syncthreads();
    }
    if (t == 0) g_off[n] = run_s;
}

// ---------------------------------------------------------------- K4: fill
__global__ void sage_fill_kernel(const int* __restrict__ ei, int E, int nn) {
    int e = blockIdx.x * blockDim.x + threadIdx.x;
    if (e < E) {
        int is64 = g_is64;
        int src = edge_val(ei, is64, e);
        int dst = edge_val(ei, is64, E + e);
        if ((unsigned)dst < (unsigned)nn && (unsigned)src < (unsigned)nn) {
            int p = atomicAdd(&g_cur[dst], 1);
            if ((unsigned)p < (unsigned)EMAX)
                g_csr[p] = src;
        }
    }
}

// ---------------------------------------------------------------- K5: aggregate x by dst (mean)
__global__ void sage_agg1_kernel(const float* __restrict__ x, int nn) {
    int gid = blockIdx.x * blockDim.x + threadIdx.x;
    int node = gid >> 4;
    if (node >= nn) return;
    int c = gid & 15;                       // float4 chunk 0..15
    int s0 = g_off[node], s1 = g_off[node + 1];
    float4 acc = make_float4(0.f, 0.f, 0.f, 0.f);
    for (int e = s0; e < s1; e++) {
        int s = g_csr[e];
        float4 v = __ldg((const float4*)(x + (size_t)s * 64) + c);
        acc.x += v.x; acc.y += v.y; acc.z += v.z; acc.w += v.w;
    }
    float inv = 1.0f / fmaxf((float)(s1 - s0), 1.0f);
    float4 o = make_float4(acc.x * inv, acc.y * inv, acc.z * inv, acc.w * inv);
    *((float4*)(g_agg1 + (size_t)node * 64) + c) = o;
}

// ---------------------------------------------------------------- K6: layer1 GEMM + folded epilogue
// Tile: 64 nodes x 64 outputs x K=64. 256 threads, each a 4x4 microtile of two
// fused GEMMs (agg1@W1l + x@W1r). Epilogue: relu + dot with W2lc/W2rc (64->2),
// reduced across the 16 lanes that share a node row via shfl_xor.
__global__ void sage_layer1_kernel(const float* __restrict__ x,
                                   const float* __restrict__ W1l,
                                   const float* __restrict__ b1,
                                   const float* __restrict__ W1r,
                                   int nn) {
    extern __shared__ float sh[];
    float* Wl_s = sh;            // [k][n]  4096
    float* Wr_s = sh + 4096;     // [k][n]  4096
    float* A1_s = sh + 8192;     // [k][m]  4096 (transposed tile of agg1)
    float* X_s  = sh + 12288;    // [k][m]  4096 (transposed tile of x)
    __shared__ float b1_s[64];
    __shared__ float Wlc_s[128];
    __shared__ float Wrc_s[128];

    int tid = threadIdx.x;
    for (int i = tid; i < 4096; i += 256) {
        Wl_s[i] = W1l[i];
        Wr_s[i] = W1r[i];
    }
    if (tid < 64)  b1_s[tid] = b1[tid];
    if (tid < 128) { Wlc_s[tid] = g_W2lc[tid]; Wrc_s[tid] = g_W2rc[tid]; }

    int m0 = blockIdx.x * 64;
    {   // load A tiles transposed into shared
        int m = tid & 63;
        int kq = tid >> 6;       // 0..3
        int gm = m0 + m;
#pragma unroll
        for (int j = 0; j < 4; j++) {
            int k4 = kq * 4 + j; // 0..15
            float4 v1 = make_float4(0.f, 0.f, 0.f, 0.f), v2 = v1;
            if (gm < nn) {
                v1 = __ldg((const float4*)(g_agg1 + (size_t)gm * 64) + k4);
                v2 = __ldg((const float4*)(x      + (size_t)gm * 64) + k4);
            }
            int kb = k4 * 4;
            A1_s[(kb + 0) * 64 + m] = v1.x; A1_s[(kb + 1) * 64 + m] = v1.y;
            A1_s[(kb + 2) * 64 + m] = v1.z; A1_s[(kb + 3) * 64 + m] = v1.w;
            X_s [(kb + 0) * 64 + m] = v2.x; X_s [(kb + 1) * 64 + m] = v2.y;
            X_s [(kb + 2) * 64 + m] = v2.z; X_s [(kb + 3) * 64 + m] = v2.w;
        }
    }
    __syncthreads();

    int n_idx = tid & 15;        // output quad
    int m_idx = tid >> 4;        // node quad
    float acc[4][4];
#pragma unroll
    for (int i = 0; i < 4; i++)
#pragma unroll
        for (int j = 0; j < 4; j++) acc[i][j] = 0.f;

#pragma unroll 16
    for (int k = 0; k < 64; k++) {
        float4 a  = *(const float4*)&A1_s[k * 64 + m_idx * 4];
        float4 xx = *(const float4*)&X_s [k * 64 + m_idx * 4];
        float4 wl = *(const float4*)&Wl_s[k * 64 + n_idx * 4];
        float4 wr = *(const float4*)&Wr_s[k * 64 + n_idx * 4];
        float av[4]  = {a.x, a.y, a.z, a.w};
        float xv[4]  = {xx.x, xx.y, xx.z, xx.w};
        float wlv[4] = {wl.x, wl.y, wl.z, wl.w};
        float wrv[4] = {wr.x, wr.y, wr.z, wr.w};
#pragma unroll
        for (int i = 0; i < 4; i++)
#pragma unroll
            for (int j = 0; j < 4; j++)
                acc[i][j] += av[i] * wlv[j] + xv[i] * wrv[j];
    }

#pragma unroll
    for (int i = 0; i < 4; i++) {
        float t0 = 0.f, t1 = 0.f, r0 = 0.f, r1 = 0.f;
#pragma unroll
        for (int j = 0; j < 4; j++) {
            int nj = n_idx * 4 + j;
            float h = acc[i][j] + b1_s[nj];
            h = fmaxf(h, 0.f);
            t0 += h * Wlc_s[nj * 2 + 0];
            t1 += h * Wlc_s[nj * 2 + 1];
            r0 += h * Wrc_s[nj * 2 + 0];
            r1 += h * Wrc_s[nj * 2 + 1];
        }
#pragma unroll
        for (int d = 8; d >= 1; d >>= 1) {
            t0 += __shfl_xor_sync(0xffffffffu, t0, d);
            t1 += __shfl_xor_sync(0xffffffffu, t1, d);
            r0 += __shfl_xor_sync(0xffffffffu, r0, d);
            r1 += __shfl_xor_sync(0xffffffffu, r1, d);
        }
        int gm = m0 + m_idx * 4 + i;
        if (n_idx == 0 && gm < nn) {
            g_t[gm] = make_float2(t0, t1);
            g_r[gm] = make_float2(r0, r1);
        }
    }
}

// ---------------------------------------------------------------- K7: aggregate t by dst + finish
__global__ void sage_final_kernel(float2* __restrict__ out, int nn) {
    int i = blockIdx.x * blockDim.x + threadIdx.x;
    if (i >= nn) return;
    int s0 = g_off[i], s1 = g_off[i + 1];
    float a0 = 0.f, a1 = 0.f;
    for (int e = s0; e < s1; e++) {
        int s = g_csr[e];
        float2 v = g_t[s];
        a0 += v.x; a1 += v.y;
    }
    float inv = 1.0f / fmaxf((float)(s1 - s0), 1.0f);
    float2 rv = g_r[i];
    out[i] = make_float2(a0 * inv + rv.x + g_bc2[0],
                         a1 * inv + rv.y + g_bc2[1]);
}

// ---------------------------------------------------------------- launch
extern "C" void kernel_launch(void* const* d_in, const int* in_sizes, int n_in,
                              void* d_out, int out_size) {
    const float* x   = (const float*)d_in[0];
    const int*   ei  = (const int*)d_in[1];     // int32 or int64 (auto-detected)
    const float* W1l = (const float*)d_in[2];
    const float* b1  = (const float*)d_in[3];
    const float* W1r = (const float*)d_in[4];
    const float* W2l = (const float*)d_in[5];
    const float* b2  = (const float*)d_in[6];
    const float* W2r = (const float*)d_in[7];
    const float* Wc  = (const float*)d_in[8];
    const float* bc  = (const float*)d_in[9];

    int nn = in_sizes[0] / 64;
    int E  = in_sizes[1] / 2;
    if (nn > NMAX) nn = NMAX;
    if (E > EMAX)  E = EMAX;

    cudaFuncSetAttribute(sage_layer1_kernel,
                         cudaFuncAttributeMaxDynamicSharedMemorySize, 65536);

    sage_detect_kernel<<<1, 32>>>(ei);
    sage_fold_kernel<<<1, 128>>>(W2l, b2, W2r, Wc, bc);
    sage_zero_cnt<<<(nn + 255) / 256, 256>>>(nn);
    sage_hist_kernel<<<(E + 255) / 256, 256>>>(ei, E, nn);
    sage_scan_kernel<<<1, 1024>>>(nn);
    sage_fill_kernel<<<(E + 255) / 256, 256>>>(ei, E, nn);
    sage_agg1_kernel<<<(nn * 16 + 255) / 256, 256>>>(x, nn);
    sage_layer1_kernel<<<(nn + 63) / 64, 256, 65536>>>(x, W1l, b1, W1r, nn);
    sage_final_kernel<<<(nn + 255) / 256, 256>>>((float2*)d_out, nn);
}

// round 5
// speedup vs baseline: 1.0100x; 1.0100x over previous
#include <cuda_runtime.h>

// GraphSAGE on GB300: CSR-gather aggregation + f32x2-packed register-tiled GEMM.
//   K_init:    cnt=0 (all blocks); block 0: dtype sniff + weight folding
//   K_hist:    cnt[dst]++ (4 edges/thread)
//   K_scanL:   per-1024-block local exclusive scan of cnt -> off, block sums
//   K_scanB:   1-block scan of 98 block sums
//   K_scanA:   off[i] += blockpre[b]; cur = off
//   K_fill:    csr[cur[dst]++] = src (4 edges/thread)
//   K_agg1:    agg1[i] = mean_{e:dst=i} x[src[e]]  (16 thr/node, unroll-2)
//   K_layer1:  h = relu(agg1@W1l + b1 + x@W1r); t = h@W2lc; r = h@W2rc
//              64x64x64 tiles, 4x4 microtiles, fma.rn.f32x2 mainloop
//   K_final:   out[i] = mean_{e:dst=i} t[src[e]] + r[i] + bc2

#define NMAX 100000
#define EMAX 1600000
#define NB_SCAN ((NMAX + 1023) / 1024)   // 98

__device__ float  g_agg1[NMAX * 64];
__device__ float2 g_t[NMAX];
__device__ float2 g_r[NMAX];
__device__ int    g_cnt[NMAX];
__device__ int    g_off[NMAX + 1];
__device__ int    g_cur[NMAX];
__device__ int    g_csr[EMAX];
__device__ int    g_bsum[NB_SCAN];
__device__ int    g_bpre[NB_SCAN];
__device__ float  g_W2lc[128];
__device__ float  g_W2rc[128];
__device__ float  g_bc2[2];
__device__ int    g_is64;

// ---- packed f32x2 helpers ------------------------------------------------
__device__ __forceinline__ unsigned long long pk2(float lo, float hi) {
    unsigned long long r;
    asm("mov.b64 %0, {%1, %2};" : "=l"(r) : "f"(lo), "f"(hi));
    return r;
}
__device__ __forceinline__ void fma2(unsigned long long& acc,
                                     unsigned long long a,
                                     unsigned long long b) {
    asm("fma.rn.f32x2 %0, %1, %2, %0;" : "+l"(acc) : "l"(a), "l"(b));
}
__device__ __forceinline__ float2 upk2(unsigned long long v) {
    float2 f;
    asm("mov.b64 {%0, %1}, %2;" : "=f"(f.x), "=f"(f.y) : "l"(v));
    return f;
}

__device__ __forceinline__ int edge_val(const int* __restrict__ w, int is64, int idx) {
    return is64 ? w[2 * idx] : w[idx];
}

// ---------------------------------------------------------------- K_init
// All blocks: zero cnt. Block 0 extra: dtype sniff (warp 4) + weight fold
// (threads 0..127). Independent work, no races.
__global__ void sage_init_kernel(const int* __restrict__ ei,
                                 const float* __restrict__ W2l,
                                 const float* __restrict__ b2,
                                 const float* __restrict__ W2r,
                                 const float* __restrict__ Wc,
                                 const float* __restrict__ bc,
                                 int n) {
    int i = blockIdx.x * blockDim.x + threadIdx.x;
    if (i < n) g_cnt[i] = 0;
    if (blockIdx.x == 0) {
        int t = threadIdx.x;
        if (t == 128) {                     // dtype sniff
            int odd_nonzero = 0;
#pragma unroll
            for (int j = 1; j < 64; j += 2)
                if (ei[j] != 0) odd_nonzero = 1;
            g_is64 = odd_nonzero ? 0 : 1;
        }
        if (t < 128) {                      // fold W2l@Wc, W2r@Wc
            int k = t >> 1, c = t & 1;
            float s = 0.f, sr = 0.f;
#pragma unroll
            for (int m = 0; m < 64; m++) {
                float w = Wc[m * 2 + c];
                s  += W2l[k * 64 + m] * w;
                sr += W2r[k * 64 + m] * w;
            }
            g_W2lc[k * 2 + c] = s;
            g_W2rc[k * 2 + c] = sr;
        }
        if (t < 2) {
            float sb = 0.f;
            for (int m = 0; m < 64; m++) sb += b2[m] * Wc[m * 2 + t];
            g_bc2[t] = sb + bc[t];
        }
    }
}

// ---------------------------------------------------------------- K_hist (4 edges/thread)
__global__ void sage_hist_kernel(const int* __restrict__ ei, int E, int nn) {
    int base = (blockIdx.x * blockDim.x + threadIdx.x) * 4;
    int is64 = g_is64;
#pragma unroll
    for (int u = 0; u < 4; u++) {
        int e = base + u;
        if (e < E) {
            int dst = edge_val(ei, is64, E + e);
            if ((unsigned)dst < (unsigned)nn)
                atomicAdd(&g_cnt[dst], 1);
        }
    }
}

// ---------------------------------------------------------------- K_scanL: per-block local scan
__global__ void sage_scan_local(int n) {
    __shared__ int wsum[32];
    int b = blockIdx.x;
    int t = threadIdx.x;
    int lane = t & 31, wid = t >> 5;
    int i = b * 1024 + t;
    int v = (i < n) ? g_cnt[i] : 0;
    int x = v;
#pragma unroll
    for (int d = 1; d < 32; d <<= 1) {
        int y = __shfl_up_sync(0xffffffffu, x, d);
        if (lane >= d) x += y;
    }
    if (lane == 31) wsum[wid] = x;
    __syncthreads();
    if (wid == 0) {
        int w = wsum[lane];
        int xw = w;
#pragma unroll
        for (int d = 1; d < 32; d <<= 1) {
            int y = __shfl_up_sync(0xffffffffu, xw, d);
            if (lane >= d) xw += y;
        }
        wsum[lane] = xw;
    }
    __syncthreads();
    int wexcl = (wid == 0) ? 0 : wsum[wid - 1];
    if (i < n) g_off[i] = (x - v) + wexcl;      // local exclusive
    if (t == 0) g_bsum[b] = 0;                   // init (overwritten below)
    __syncthreads();
    if (t == 1023) g_bsum[b] = wsum[31];         // block total
}

// ---------------------------------------------------------------- K_scanB: scan block sums (1 block)
__global__ void sage_scan_block(int nb, int n) {
    __shared__ int wsum[32];
    int t = threadIdx.x;                 // 128 threads
    int lane = t & 31, wid = t >> 5;
    int v = (t < nb) ? g_bsum[t] : 0;
    int x = v;
#pragma unroll
    for (int d = 1; d < 32; d <<= 1) {
        int y = __shfl_up_sync(0xffffffffu, x, d);
        if (lane >= d) x += y;
    }
    if (lane == 31) wsum[wid] = x;
    __syncthreads();
    if (wid == 0) {
        int w = (lane < 4) ? wsum[lane] : 0;
        int xw = w;
#pragma unroll
        for (int d = 1; d < 32; d <<= 1) {
            int y = __shfl_up_sync(0xffffffffu, xw, d);
            if (lane >= d) xw += y;
        }
        wsum[lane] = xw;
    }
    __syncthreads();
    int wexcl = (wid == 0) ? 0 : wsum[wid - 1];
    if (t < nb) g_bpre[t] = (x - v) + wexcl;
    if (t == nb - 1) g_off[n] = x + wexcl;       // grand total
}

// ---------------------------------------------------------------- K_scanA: add block prefixes
__global__ void sage_scan_add(int n) {
    int b = blockIdx.x;
    int i = b * 1024 + threadIdx.x;
    if (i < n) {
        int o = g_off[i] + g_bpre[b];
        g_off[i] = o;
        g_cur[i] = o;
    }
}

// ---------------------------------------------------------------- K_fill (4 edges/thread)
__global__ void sage_fill_kernel(const int* __restrict__ ei, int E, int nn) {
    int base = (blockIdx.x * blockDim.x + threadIdx.x) * 4;
    int is64 = g_is64;
#pragma unroll
    for (int u = 0; u < 4; u++) {
        int e = base + u;
        if (e < E) {
            int src = edge_val(ei, is64, e);
            int dst = edge_val(ei, is64, E + e);
            if ((unsigned)dst < (unsigned)nn && (unsigned)src < (unsigned)nn) {
                int p = atomicAdd(&g_cur[dst], 1);
                if ((unsigned)p < (unsigned)EMAX)
                    g_csr[p] = src;
            }
        }
    }
}

// ---------------------------------------------------------------- K_agg1: mean-gather x (unroll-2)
__global__ void sage_agg1_kernel(const float* __restrict__ x, int nn) {
    int gid = blockIdx.x * blockDim.x + threadIdx.x;
    int node = gid >> 4;
    if (node >= nn) return;
    int c = gid & 15;
    int s0 = g_off[node], s1 = g_off[node + 1];
    float4 acc0 = make_float4(0.f, 0.f, 0.f, 0.f);
    float4 acc1 = make_float4(0.f, 0.f, 0.f, 0.f);
    int e = s0;
    for (; e + 1 < s1; e += 2) {
        int sA = g_csr[e], sB = g_csr[e + 1];
        float4 vA = __ldg((const float4*)(x + (size_t)sA * 64) + c);
        float4 vB = __ldg((const float4*)(x + (size_t)sB * 64) + c);
        acc0.x += vA.x; acc0.y += vA.y; acc0.z += vA.z; acc0.w += vA.w;
        acc1.x += vB.x; acc1.y += vB.y; acc1.z += vB.z; acc1.w += vB.w;
    }
    if (e < s1) {
        int sA = g_csr[e];
        float4 vA = __ldg((const float4*)(x + (size_t)sA * 64) + c);
        acc0.x += vA.x; acc0.y += vA.y; acc0.z += vA.z; acc0.w += vA.w;
    }
    float inv = 1.0f / fmaxf((float)(s1 - s0), 1.0f);
    float4 o = make_float4((acc0.x + acc1.x) * inv, (acc0.y + acc1.y) * inv,
                           (acc0.z + acc1.z) * inv, (acc0.w + acc1.w) * inv);
    *((float4*)(g_agg1 + (size_t)node * 64) + c) = o;
}

// ---------------------------------------------------------------- K_layer1: fused GEMMs + epilogue
__global__ void sage_layer1_kernel(const float* __restrict__ x,
                                   const float* __restrict__ W1l,
                                   const float* __restrict__ b1,
                                   const float* __restrict__ W1r,
                                   int nn) {
    extern __shared__ float sh[];
    float* Wl_s = sh;            // [k][n]  4096
    float* Wr_s = sh + 4096;     // [k][n]  4096
    float* A1_s = sh + 8192;     // [k][m]  4096
    float* X_s  = sh + 12288;    // [k][m]  4096
    __shared__ float b1_s[64];
    __shared__ float Wlc_s[128];
    __shared__ float Wrc_s[128];

    int tid = threadIdx.x;
    for (int i = tid; i < 4096; i += 256) {
        Wl_s[i] = W1l[i];
        Wr_s[i] = W1r[i];
    }
    if (tid < 64)  b1_s[tid] = b1[tid];
    if (tid < 128) { Wlc_s[tid] = g_W2lc[tid]; Wrc_s[tid] = g_W2rc[tid]; }

    int m0 = blockIdx.x * 64;
    {
        int m = tid & 63;
        int kq = tid >> 6;
        int gm = m0 + m;
#pragma unroll
        for (int j = 0; j < 4; j++) {
            int k4 = kq * 4 + j;
            float4 v1 = make_float4(0.f, 0.f, 0.f, 0.f), v2 = v1;
            if (gm < nn) {
                v1 = __ldg((const float4*)(g_agg1 + (size_t)gm * 64) + k4);
                v2 = __ldg((const float4*)(x      + (size_t)gm * 64) + k4);
            }
            int kb = k4 * 4;
            A1_s[(kb + 0) * 64 + m] = v1.x; A1_s[(kb + 1) * 64 + m] = v1.y;
            A1_s[(kb + 2) * 64 + m] = v1.z; A1_s[(kb + 3) * 64 + m] = v1.w;
            X_s [(kb + 0) * 64 + m] = v2.x; X_s [(kb + 1) * 64 + m] = v2.y;
            X_s [(kb + 2) * 64 + m] = v2.z; X_s [(kb + 3) * 64 + m] = v2.w;
        }
    }
    __syncthreads();

    int n_idx = tid & 15;
    int m_idx = tid >> 4;
    // acc2[i][jp] packs outputs (j=2jp, 2jp+1) for node-row i
    unsigned long long acc2[4][2];
    unsigned long long z = pk2(0.f, 0.f);
#pragma unroll
    for (int i = 0; i < 4; i++) { acc2[i][0] = z; acc2[i][1] = z; }

#pragma unroll 16
    for (int k = 0; k < 64; k++) {
        float4 a  = *(const float4*)&A1_s[k * 64 + m_idx * 4];
        float4 xx = *(const float4*)&X_s [k * 64 + m_idx * 4];
        float4 wl = *(const float4*)&Wl_s[k * 64 + n_idx * 4];
        float4 wr = *(const float4*)&Wr_s[k * 64 + n_idx * 4];
        unsigned long long wl01 = pk2(wl.x, wl.y), wl23 = pk2(wl.z, wl.w);
        unsigned long long wr01 = pk2(wr.x, wr.y), wr23 = pk2(wr.z, wr.w);
        float av[4] = {a.x, a.y, a.z, a.w};
        float xv[4] = {xx.x, xx.y, xx.z, xx.w};
#pragma unroll
        for (int i = 0; i < 4; i++) {
            unsigned long long ab = pk2(av[i], av[i]);
            unsigned long long xb = pk2(xv[i], xv[i]);
            fma2(acc2[i][0], ab, wl01);
            fma2(acc2[i][0], xb, wr01);
            fma2(acc2[i][1], ab, wl23);
            fma2(acc2[i][1], xb, wr23);
        }
    }

#pragma unroll
    for (int i = 0; i < 4; i++) {
        float2 p0 = upk2(acc2[i][0]);
        float2 p1 = upk2(acc2[i][1]);
        float accv[4] = {p0.x, p0.y, p1.x, p1.y};
        float t0 = 0.f, t1 = 0.f, r0 = 0.f, r1 = 0.f;
#pragma unroll
        for (int j = 0; j < 4; j++) {
            int nj = n_idx * 4 + j;
            float h = fmaxf(accv[j] + b1_s[nj], 0.f);
            t0 += h * Wlc_s[nj * 2 + 0];
            t1 += h * Wlc_s[nj * 2 + 1];
            r0 += h * Wrc_s[nj * 2 + 0];
            r1 += h * Wrc_s[nj * 2 + 1];
        }
#pragma unroll
        for (int d = 8; d >= 1; d >>= 1) {
            t0 += __shfl_xor_sync(0xffffffffu, t0, d);
            t1 += __shfl_xor_sync(0xffffffffu, t1, d);
            r0 += __shfl_xor_sync(0xffffffffu, r0, d);
            r1 += __shfl_xor_sync(0xffffffffu, r1, d);
        }
        int gm = m0 + m_idx * 4 + i;
        if (n_idx == 0 && gm < nn) {
            g_t[gm] = make_float2(t0, t1);
            g_r[gm] = make_float2(r0, r1);
        }
    }
}

// ---------------------------------------------------------------- K_final
__global__ void sage_final_kernel(float2* __restrict__ out, int nn) {
    int i = blockIdx.x * blockDim.x + threadIdx.x;
    if (i >= nn) return;
    int s0 = g_off[i], s1 = g_off[i + 1];
    float a0 = 0.f, a1 = 0.f;
    for (int e = s0; e < s1; e++) {
        int s = g_csr[e];
        float2 v = g_t[s];
        a0 += v.x; a1 += v.y;
    }
    float inv = 1.0f / fmaxf((float)(s1 - s0), 1.0f);
    float2 rv = g_r[i];
    out[i] = make_float2(a0 * inv + rv.x + g_bc2[0],
                         a1 * inv + rv.y + g_bc2[1]);
}

// ---------------------------------------------------------------- launch
extern "C" void kernel_launch(void* const* d_in, const int* in_sizes, int n_in,
                              void* d_out, int out_size) {
    const float* x   = (const float*)d_in[0];
    const int*   ei  = (const int*)d_in[1];     // int32 or int64 (auto-detected)
    const float* W1l = (const float*)d_in[2];
    const float* b1  = (const float*)d_in[3];
    const float* W1r = (const float*)d_in[4];
    const float* W2l = (const float*)d_in[5];
    const float* b2  = (const float*)d_in[6];
    const float* W2r = (const float*)d_in[7];
    const float* Wc  = (const float*)d_in[8];
    const float* bc  = (const float*)d_in[9];

    int nn = in_sizes[0] / 64;
    int E  = in_sizes[1] / 2;
    if (nn > NMAX) nn = NMAX;
    if (E > EMAX)  E = EMAX;
    int nb = (nn + 1023) / 1024;

    cudaFuncSetAttribute(sage_layer1_kernel,
                         cudaFuncAttributeMaxDynamicSharedMemorySize, 65536);

    sage_init_kernel<<<(nn + 255) / 256, 256>>>(ei, W2l, b2, W2r, Wc, bc, nn);
    sage_hist_kernel<<<(E / 4 + 255) / 256, 256>>>(ei, E, nn);
    sage_scan_local<<<nb, 1024>>>(nn);
    sage_scan_block<<<1, 128>>>(nb, nn);
    sage_scan_add<<<nb, 1024>>>(nn);
    sage_fill_kernel<<<(E / 4 + 255) / 256, 256>>>(ei, E, nn);
    sage_agg1_kernel<<<(nn * 16 + 255) / 256, 256>>>(x, nn);
    sage_layer1_kernel<<<(nn + 63) / 64, 256, 65536>>>(x, W1l, b1, W1r, nn);
    sage_final_kernel<<<(nn + 255) / 256, 256>>>((float2*)d_out, nn);
}